// round 11
// baseline (speedup 1.0000x reference)
#include <cuda_runtime.h>

#define NN   28      // nodes
#define NA   32      // padded A row stride
#define RPB  64      // rows per block
#define TPB  256     // threads: (q:8 comps-blocks) x (h:2 s-halves) x (g:16 row-groups)
#define SR   68      // transposed x/z stage row stride
#define KH   14      // split-K half length (NN/2)

// pick component of a float4 with a compile-time constant index
__device__ __forceinline__ float f4c(const float4& v, int c) {
    return (c == 0) ? v.x : (c == 1) ? v.y : (c == 2) ? v.z : v.w;
}

// ---------------------------------------------------------------------------
// Fused kernel. Per block: stage 64 x-rows transposed, build normalized
// adjacency in shared (dtype-probed edge_index), collapse MLP to (cp,cn),
// then out = A . f(A . x) + b2.
// Thread (q = t&7, h = (t>>3)&1, g = t>>4): comps [4q,4q+4), rows [4g,4g+4),
// s-half h. Partial sums over s combined via shfl_xor(8) within the warp.
// ---------------------------------------------------------------------------
__global__ void __launch_bounds__(TPB, 5) gcn_fused_kernel(
    const float* __restrict__ x, float* __restrict__ out,
    const int* __restrict__ ei32, int n_elems,
    const float* __restrict__ W1, const float* __restrict__ b1,
    const float* __restrict__ W2, const float* __restrict__ b2,
    int H, int B)
{
    __shared__ float As[NN * NA];     // transposed adjacency: As[s*NA+d]=A[d][s]
    __shared__ float xs[NN * SR];     // transposed x, then z
    __shared__ float deg[NN];
    __shared__ float dinv[NN];
    __shared__ float wred[128];
    __shared__ float s_cp, s_cn;

    const int t  = threadIdx.x;
    const int q  = t & 7;             // comp block: comps [4q, 4q+4)
    const int h  = (t >> 3) & 1;      // s-half
    const int g  = t >> 4;            // row-group 0..15
    const int r0 = g * 4;
    const int s0 = h * KH;

    // ---- init shared ----
    if (t < NN) deg[t] = 1.0f;        // self-loop contributes 1
    for (int i = t; i < NN * NA; i += TPB) As[i] = 0.0f;

    // ---- stage x transposed: xs[c*SR + r] = x[row r, comp c] ----
    const long long rowbase = (long long)blockIdx.x * RPB;
    int nrows = (int)(B - rowbase); if (nrows > RPB) nrows = RPB;
    const float* gx = x + rowbase * NN;
    for (int i = t; i < nrows * NN; i += TPB) {
        int r = i / NN, c = i - r * NN;
        xs[c * SR + r] = gx[i];
    }

    // ---- dtype probe: int64 LE with ids <28 has all-zero odd int32 words ----
    int found = 0;
    for (int i = 2 * t + 1; i < n_elems; i += 2 * TPB)
        if (ei32[i] != 0) found = 1;
    const int is32 = __syncthreads_or(found);

    const int E = n_elems / 2;
    const int stride  = is32 ? 1 : 2;
    const int dstbase = is32 ? E : 2 * E;

    // ---- degrees ----
    for (int e = t; e < E; e += TPB) {
        int d = ei32[dstbase + stride * e];
        if (d >= 0 && d < NN) atomicAdd(&deg[d], 1.0f);
    }
    __syncthreads();
    if (t < NN) dinv[t] = deg[t] > 0.0f ? rsqrtf(deg[t]) : 0.0f;
    __syncthreads();

    // ---- adjacency, built directly transposed ----
    for (int e = t; e < E; e += TPB) {
        int s = ei32[stride * e];
        int d = ei32[dstbase + stride * e];
        if (s >= 0 && s < NN && d >= 0 && d < NN)
            atomicAdd(&As[s * NA + d], dinv[s] * dinv[d]);
    }
    if (t < NN) atomicAdd(&As[t * NA + t], dinv[t] * dinv[t]);

    // ---- MLP collapse ----
    int gflag = 0;
    if (t < 64) {
        float p = 0.0f, n = 0.0f;
        for (int o = t; o < H; o += 64) {
            float w1 = W1[o], w2 = W2[o];
            if (w1 > 0.0f) p += w1 * w2;
            else           n += w1 * w2;
            if (b1[o] != 0.0f) gflag = 1;
        }
        wred[t] = p; wred[64 + t] = n;
    }
    const int general = __syncthreads_or(gflag);   // also fences As atomics
    if (t == 0) {
        float cpa = 0.0f, cna = 0.0f;
        #pragma unroll
        for (int i = 0; i < 64; i++) { cpa += wred[i]; cna += wred[64 + i]; }
        s_cp = cpa; s_cn = cna;
    }
    __syncthreads();
    const float cp = s_cp, cn = s_cn, b2v = b2[0];

    const float* ap = As + q * 4;

    // ---- matvec 1 (partial over s-half): acc += A[s][4q+j] * x[row][s] ----
    float acc[4][4];
    #pragma unroll
    for (int rw = 0; rw < 4; rw++)
        #pragma unroll
        for (int j = 0; j < 4; j++) acc[rw][j] = 0.0f;

    #pragma unroll
    for (int si = 0; si < KH; si++) {
        const int s = s0 + si;
        const float4 xv = *(const float4*)(xs + s * SR + r0);
        const float4 a  = *(const float4*)(ap + s * NA);
        #pragma unroll
        for (int rw = 0; rw < 4; rw++) {
            const float xr = f4c(xv, rw);
            acc[rw][0] = fmaf(a.x, xr, acc[rw][0]);
            acc[rw][1] = fmaf(a.y, xr, acc[rw][1]);
            acc[rw][2] = fmaf(a.z, xr, acc[rw][2]);
            acc[rw][3] = fmaf(a.w, xr, acc[rw][3]);
        }
    }

    // ---- combine s-halves (partner = lane ^ 8, same warp) ----
    #pragma unroll
    for (int rw = 0; rw < 4; rw++)
        #pragma unroll
        for (int j = 0; j < 4; j++)
            acc[rw][j] += __shfl_xor_sync(0xFFFFFFFFu, acc[rw][j], 8);

    // ---- z = f(y) ----
    if (!general) {
        #pragma unroll
        for (int rw = 0; rw < 4; rw++)
            #pragma unroll
            for (int j = 0; j < 4; j++)
                acc[rw][j] = cp * fmaxf(acc[rw][j], 0.0f)
                           + cn * fminf(acc[rw][j], 0.0f);
    } else {
        #pragma unroll
        for (int rw = 0; rw < 4; rw++)
            #pragma unroll
            for (int j = 0; j < 4; j++) {
                float v = acc[rw][j], a2 = 0.0f;
                for (int o = 0; o < H; o++)
                    a2 = fmaf(W2[o], fmaxf(fmaf(W1[o], v, b1[o]), 0.0f), a2);
                acc[rw][j] = a2;
            }
    }

    __syncthreads();   // all matvec-1 reads of xs complete before z overwrite

    // ---- publish z transposed (h==0 writers only; both halves identical) ----
    if (h == 0) {
        #pragma unroll
        for (int j = 0; j < 4; j++) {
            int d = q * 4 + j;
            if (d < NN)
                *(float4*)(xs + d * SR + r0) =
                    make_float4(acc[0][j], acc[1][j], acc[2][j], acc[3][j]);
        }
    }
    __syncthreads();

    // ---- matvec 2 (partial over s-half) ----
    #pragma unroll
    for (int rw = 0; rw < 4; rw++)
        #pragma unroll
        for (int j = 0; j < 4; j++) acc[rw][j] = 0.0f;

    #pragma unroll
    for (int si = 0; si < KH; si++) {
        const int s = s0 + si;
        const float4 zv = *(const float4*)(xs + s * SR + r0);
        const float4 a  = *(const float4*)(ap + s * NA);
        #pragma unroll
        for (int rw = 0; rw < 4; rw++) {
            const float zr = f4c(zv, rw);
            acc[rw][0] = fmaf(a.x, zr, acc[rw][0]);
            acc[rw][1] = fmaf(a.y, zr, acc[rw][1]);
            acc[rw][2] = fmaf(a.z, zr, acc[rw][2]);
            acc[rw][3] = fmaf(a.w, zr, acc[rw][3]);
        }
    }

    // ---- combine halves, add bias ----
    #pragma unroll
    for (int rw = 0; rw < 4; rw++)
        #pragma unroll
        for (int j = 0; j < 4; j++)
            acc[rw][j] = b2v + acc[rw][j]
                       + __shfl_xor_sync(0xFFFFFFFFu, acc[rw][j], 8);

    // ---- stores: h==0 -> rows r0,r0+1 ; h==1 -> rows r0+2,r0+3 ----
    if (q * 4 < NN) {
        #pragma unroll
        for (int k = 0; k < 2; k++) {
            int rw = h * 2 + k;
            int lr = r0 + rw;
            if (lr < nrows) {
                float* op = out + (rowbase + lr) * NN + q * 4;
                *(float4*)op = make_float4(acc[rw][0], acc[rw][1],
                                           acc[rw][2], acc[rw][3]);
            }
        }
    }
}

extern "C" void kernel_launch(void* const* d_in, const int* in_sizes, int n_in,
                              void* d_out, int out_size)
{
    const float* x  = (const float*)d_in[0];
    const int*   ei = (const int*)d_in[1];     // int32 view; dtype probed on-device
    const float* W1 = (const float*)d_in[2];
    const float* b1 = (const float*)d_in[3];
    const float* W2 = (const float*)d_in[4];
    const float* b2 = (const float*)d_in[5];
    float* out = (float*)d_out;

    int B = in_sizes[0] / NN;
    int n_edge_elems = in_sizes[1];
    int H = in_sizes[3];

    int grid = (B + RPB - 1) / RPB;
    gcn_fused_kernel<<<grid, TPB>>>(x, out, ei, n_edge_elems,
                                    W1, b1, W2, b2, H, B);
}